// round 1
// baseline (speedup 1.0000x reference)
#include <cuda_runtime.h>
#include <stdint.h>

// XFlatRGBExtractorOp — masked channel select + stack.
// B=16, H=W=1536. Output (B,3,H,W) f32.
//   ch0 = r_mask ? xtrans[:,0] : chroma_pred[:,0]
//   ch1 = green_pred[:,0]
//   ch2 = b_mask ? xtrans[:,2] : chroma_pred[:,1]
// Masks are 6x6 tiled patterns.

#define Bsz 16
#define H 1536
#define W 1536
#define P (H * W)          // 2359296 floats per plane
#define P4 (P / 4)         // 589824 float4 per plane
#define W4 (W / 4)         // 384 float4 per row

// 6-bit row masks: bit c set => take xtrans at column (w % 6) == c.
// R_POS rows: 0:{4} 1:{0,2} 2:{4} 3:{1} 4:{3,5} 5:{1}
// B_POS rows: 0:{1} 1:{3,5} 2:{1} 3:{4} 4:{0,2} 5:{4}
__constant__ unsigned c_rmask[6] = {0x10u, 0x05u, 0x10u, 0x02u, 0x28u, 0x02u};
__constant__ unsigned c_bmask[6] = {0x02u, 0x28u, 0x02u, 0x10u, 0x05u, 0x10u};

__global__ __launch_bounds__(256) void xflat_rgb_kernel(
    const float4* __restrict__ green,   // B * P4
    const float4* __restrict__ xtrans,  // B * 3 * P4
    const float4* __restrict__ chroma,  // B * 2 * P4
    float4* __restrict__ out)           // B * 3 * P4
{
    const int i = blockIdx.x * 256 + threadIdx.x;   // float4 index within plane
    if (i >= P4) return;
    const int plane = blockIdx.y;                   // 0..3B-1
    const int b = plane / 3;
    const int c = plane - 3 * b;

    const size_t oidx = (size_t)plane * P4 + i;

    if (c == 1) {
        // green copy (uniform branch across the whole plane's blocks)
        out[oidx] = green[(size_t)b * P4 + i];
        return;
    }

    // row / column phase within the 6x6 tile
    const int h  = i / W4;
    const int w4 = (i - h * W4) * 4;                // starting column of this float4
    const int r  = h % 6;
    const int w6 = w4 % 6;                          // 0, 2, or 4

    const unsigned rowm = (c == 0) ? c_rmask[r] : c_bmask[r];
    // rotate so that bit k = mask for lane k (columns w6..w6+3 with wrap at 6)
    const unsigned sel = (rowm >> w6) | (rowm << (6 - w6));

    const int xch = (c == 0) ? 0 : 2;               // xtrans channel
    const int pch = (c == 0) ? 0 : 1;               // chroma channel

    const float4 a = xtrans[((size_t)b * 3 + xch) * P4 + i];
    const float4 p = chroma[((size_t)b * 2 + pch) * P4 + i];

    float4 o;
    o.x = (sel & 1u) ? a.x : p.x;
    o.y = (sel & 2u) ? a.y : p.y;
    o.z = (sel & 4u) ? a.z : p.z;
    o.w = (sel & 8u) ? a.w : p.w;
    out[oidx] = o;
}

extern "C" void kernel_launch(void* const* d_in, const int* in_sizes, int n_in,
                              void* d_out, int out_size)
{
    const float4* green  = (const float4*)d_in[0];  // (B,1,H,W)
    const float4* xtrans = (const float4*)d_in[1];  // (B,3,H,W)
    const float4* chroma = (const float4*)d_in[2];  // (B,2,H,W)
    float4* out = (float4*)d_out;                   // (B,3,H,W)

    dim3 grid((P4 + 255) / 256, Bsz * 3, 1);
    xflat_rgb_kernel<<<grid, 256>>>(green, xtrans, chroma, out);
}